// round 9
// baseline (speedup 1.0000x reference)
#include <cuda_runtime.h>
#include <cuda_bf16.h>
#include <math.h>

// Problem shape (fixed for this problem instance)
#define B_    4
#define NA    8192
#define NB_   8192
#define D_    256
#define TOPK  8
#define NCELL 512      // 8x8x8 grid of cells, cell side 16 (in //16 coords)

// ---------------------------------------------------------------------------
// Scratch (static device globals; no dynamic allocation allowed)
// ---------------------------------------------------------------------------
__device__ float g_P[B_ * NA * D_];        // af @ W1b^T + b1      [32768,256]
__device__ float g_Q[B_ * NB_ * D_];       // bf @ (W1a-W1b)^T     [32768,256]
__device__ float g_S[B_ * NA * D_];        // sum_k relu(Q+P)*dw   [32768,256]
__device__ float g_WdT[D_ * D_];           // (W1a-W1b)^T  [c,d]   (tf32-rounded)
__device__ float g_W1bT[D_ * D_];          // W1b^T        [c,d]   (tf32-rounded)
__device__ float g_W2T[D_ * D_];           // W2^T         [d,e]   (tf32-rounded)
__device__ int   g_idx[B_ * NA * TOPK];
__device__ float g_dw[B_ * NA * TOPK];

// spatial grid scratch
__device__ int      g_cellcnt[B_ * NCELL];
__device__ int      g_cellstart[B_ * (NCELL + 1)];
__device__ int      g_cellcur[B_ * NCELL];
__device__ uint2    g_pts[B_ * NB_];       // cell-sorted (packed coord, index)
__device__ unsigned g_cbp[B_ * NB_];       // packed //16 coords, original order

// ---------------------------------------------------------------------------
// tf32 helpers
// ---------------------------------------------------------------------------
__device__ __forceinline__ unsigned f2tf32(float v) {
    unsigned r;
    asm("cvt.rna.tf32.f32 %0, %1;" : "=r"(r) : "f"(v));
    return r;
}

// ---------------------------------------------------------------------------
// Weight preprocessing (outputs pre-rounded to the tf32 grid so the GEMM can
// consume B fragments without a cvt — truncation of pre-rounded = identity)
// ---------------------------------------------------------------------------
__global__ void prep_w_kernel(const float* __restrict__ w1,
                              const float* __restrict__ w2,
                              float* __restrict__ WdT,
                              float* __restrict__ W1bT,
                              float* __restrict__ W2T) {
    int i = blockIdx.x;
    int t = threadIdx.x;
    float a = w1[t * 512 + i];
    float b = w1[t * 512 + 256 + i];
    WdT[i * 256 + t]  = __uint_as_float(f2tf32(a - b));
    W1bT[i * 256 + t] = __uint_as_float(f2tf32(b));
    W2T[i * 256 + t]  = __uint_as_float(f2tf32(w2[t * 256 + i]));
}

// ---------------------------------------------------------------------------
// Spatial grid build: zero -> histogram -> scan -> scatter
// ---------------------------------------------------------------------------
__global__ void zero_cnt_kernel(int* __restrict__ cnt) {
    cnt[blockIdx.x * blockDim.x + threadIdx.x] = 0;
}

__global__ void hist_kernel(const int* __restrict__ coords_b,
                            unsigned* __restrict__ cbp,
                            int* __restrict__ cnt) {
    const int i = blockIdx.x * blockDim.x + threadIdx.x;   // 0..B*NB-1
    const int b = i >> 13;
    const int* cb = coords_b + (size_t)i * 3;
    const unsigned x = ((unsigned)cb[0]) >> 4;
    const unsigned y = ((unsigned)cb[1]) >> 4;
    const unsigned z = ((unsigned)cb[2]) >> 4;
    cbp[i] = x | (y << 8) | (z << 16);
    const int cell = (int)(((x >> 4) << 6) | ((y >> 4) << 3) | (z >> 4));
    atomicAdd(&cnt[b * NCELL + cell], 1);
}

__global__ void scan_kernel(const int* __restrict__ cnt,
                            int* __restrict__ cellstart,
                            int* __restrict__ cur) {
    __shared__ int sc[NCELL];
    const int b = blockIdx.x, t = threadIdx.x;
    const int v = cnt[b * NCELL + t];
    sc[t] = v;
    __syncthreads();
    for (int off = 1; off < NCELL; off <<= 1) {
        int x = (t >= off) ? sc[t - off] : 0;
        __syncthreads();
        sc[t] += x;
        __syncthreads();
    }
    cellstart[b * (NCELL + 1) + t + 1] = sc[t];
    if (t == 0) cellstart[b * (NCELL + 1)] = 0;
    cur[b * NCELL + t] = sc[t] - v;   // exclusive
}

__global__ void scatter_kernel(const unsigned* __restrict__ cbp,
                               int* __restrict__ cur,
                               uint2* __restrict__ pts) {
    const int i = blockIdx.x * blockDim.x + threadIdx.x;
    const int b = i >> 13, j = i & 8191;
    const unsigned p = cbp[i];
    const int cell = (int)((((p >> 4) & 7u) << 6) | (((p >> 12) & 7u) << 3) | ((p >> 20) & 7u));
    const int pos = atomicAdd(&cur[b * NCELL + cell], 1);
    pts[(size_t)b * NB_ + pos] = make_uint2(p, (unsigned)j);
}

// ---------------------------------------------------------------------------
// kNN helpers
// ---------------------------------------------------------------------------
__device__ __forceinline__ void insert8(unsigned best[8], unsigned key) {
    if (key < best[7]) {
        best[7] = key;
#pragma unroll
        for (int t = 7; t > 0; --t) {
            unsigned lo = min(best[t - 1], best[t]);
            unsigned hi = max(best[t - 1], best[t]);
            best[t - 1] = lo;
            best[t]     = hi;
        }
    }
}

__device__ __forceinline__ unsigned merge8(unsigned best[8], int lane) {
    unsigned sel = 0;
#pragma unroll
    for (int r = 0; r < 8; ++r) {
        const unsigned v = best[0];
        const unsigned m = __reduce_min_sync(0xFFFFFFFFu, v);
        if (lane == r) sel = m;
        if (v == m) {
#pragma unroll
            for (int t = 0; t < 7; ++t) best[t] = best[t + 1];
            best[7] = 0xFFFFFFFFu;
        }
    }
    return sel;
}

// ---------------------------------------------------------------------------
// Grid kNN: one warp per query; certified exact (brute fallback if the 8th
// neighbor could lie outside the scanned neighborhood).
// ---------------------------------------------------------------------------
__global__ void knn_grid_kernel(const int* __restrict__ coords_a,
                                const unsigned* __restrict__ cbp,
                                const uint2* __restrict__ pts,
                                const int* __restrict__ cellstart,
                                int* __restrict__ idx_out,
                                float* __restrict__ dw_out) {
    const int b = blockIdx.y;
    const int warp = threadIdx.x >> 5;
    const int lane = threadIdx.x & 31;
    const int n = blockIdx.x * 8 + warp;

    const int* ca = coords_a + ((size_t)b * NA + n) * 3;
    const unsigned qx = ((unsigned)ca[0]) >> 4;
    const unsigned qy = ((unsigned)ca[1]) >> 4;
    const unsigned qz = ((unsigned)ca[2]) >> 4;
    const unsigned qp = qx | (qy << 8) | (qz << 16);

    const int cx = (int)(qx >> 4), cy = (int)(qy >> 4), cz = (int)(qz >> 4);
    const int x0 = max(cx - 1, 0), x1 = min(cx + 1, 7);
    const int y0 = max(cy - 1, 0), y1 = min(cy + 1, 7);
    const int z0 = max(cz - 1, 0), z1 = min(cz + 1, 7);

    const int sbase = b * (NCELL + 1);
    const uint2* ptsb = pts + (size_t)b * NB_;

    unsigned best[8];
#pragma unroll
    for (int t = 0; t < 8; ++t) best[t] = 0xFFFFFFFFu;

    for (int x = x0; x <= x1; ++x)
        for (int y = y0; y <= y1; ++y)
            for (int z = z0; z <= z1; ++z) {
                const int c = (x << 6) | (y << 3) | z;
                const int s = __ldg(&cellstart[sbase + c]);
                const int e = __ldg(&cellstart[sbase + c + 1]);
                for (int o = s + lane; o < e; o += 32) {
                    const uint2 pt = ptsb[o];
                    const unsigned ad = __vabsdiffu4(pt.x, qp);
                    const unsigned d2 = (unsigned)__dp4a((int)ad, (int)ad, 0);
                    insert8(best, (d2 << 13) | pt.y);
                }
            }

    unsigned sel = merge8(best, lane);

    const unsigned d2_8 = __shfl_sync(0xFFFFFFFFu, sel, 7) >> 13;
    int mo = 0x7FFFFFFF;
    if (x0 > 0) { int d = (int)qx - (16 * x0 - 1); mo = min(mo, d * d); }
    if (x1 < 7) { int d = 16 * (x1 + 1) - (int)qx; mo = min(mo, d * d); }
    if (y0 > 0) { int d = (int)qy - (16 * y0 - 1); mo = min(mo, d * d); }
    if (y1 < 7) { int d = 16 * (y1 + 1) - (int)qy; mo = min(mo, d * d); }
    if (z0 > 0) { int d = (int)qz - (16 * z0 - 1); mo = min(mo, d * d); }
    if (z1 < 7) { int d = 16 * (z1 + 1) - (int)qz; mo = min(mo, d * d); }

    if (d2_8 >= (unsigned)mo) {   // warp-uniform; vanishingly rare
#pragma unroll
        for (int t = 0; t < 8; ++t) best[t] = 0xFFFFFFFFu;
        const unsigned* cb = cbp + (size_t)b * NB_;
        for (int j = lane; j < NB_; j += 32) {
            const unsigned p = __ldg(&cb[j]);
            const unsigned ad = __vabsdiffu4(p, qp);
            const unsigned d2 = (unsigned)__dp4a((int)ad, (int)ad, 0);
            insert8(best, (d2 << 13) | (unsigned)j);
        }
        sel = merge8(best, lane);
    }

    if (lane < 8) {
        const int j = (int)(sel & 8191u);
        const float dist = sqrtf((float)(sel >> 13)) * (1.0f / 128.0f);
        const float dwv = 0.5f - fminf(dist, 0.5f);
        const size_t o = ((size_t)b * NA + n) * 8 + lane;
        idx_out[o] = j;
        dw_out[o]  = dwv;
    }
}

// ---------------------------------------------------------------------------
// TF32 tensor-core GEMM with 4-stage cp.async pipeline.
// C[M,256] = A[M,256] @ B[256,256] (+ bscale*bias)
// BM=BN=128, BK=16, 256 threads, 8 warps as 2x4 (warp tile 64x32).
// B is pre-rounded to tf32 grid (no cvt on B frags); A frags cvt.rna at LDS.
// Smem (dynamic): As [4][128][20] f32, Bs [4][16][136] f32 = 75,776 B.
// ---------------------------------------------------------------------------
__device__ __forceinline__ void mma_tf32(float* c,
                                         unsigned a0, unsigned a1, unsigned a2, unsigned a3,
                                         unsigned b0, unsigned b1) {
    asm volatile(
        "mma.sync.aligned.m16n8k8.row.col.f32.tf32.tf32.f32 "
        "{%0,%1,%2,%3}, {%4,%5,%6,%7}, {%8,%9}, {%0,%1,%2,%3};"
        : "+f"(c[0]), "+f"(c[1]), "+f"(c[2]), "+f"(c[3])
        : "r"(a0), "r"(a1), "r"(a2), "r"(a3), "r"(b0), "r"(b1));
}

#define SA 20
#define SB 136
#define AS_STG (128 * SA)     // 2560 words / stage
#define BS_STG (16 * SB)      // 2176 words / stage
#define NSTAGE 4
#define GEMM_SMEM ((NSTAGE * (AS_STG + BS_STG)) * 4)   // 75,776 bytes

#define CP_ASYNC16(dst_u32, src_ptr) \
    asm volatile("cp.async.cg.shared.global [%0], [%1], 16;" \
                 :: "r"(dst_u32), "l"(src_ptr))
#define CP_COMMIT()  asm volatile("cp.async.commit_group;")
#define CP_WAIT2()   asm volatile("cp.async.wait_group 2;")

__global__ __launch_bounds__(256, 2)
void mma_gemm_kernel(const float* __restrict__ A, const float* __restrict__ Bm,
                     float* __restrict__ C, int ldc,
                     const float* __restrict__ bias, float bscale) {
    const int K = 256;
    extern __shared__ float sm[];
    float* Asm = sm;                       // NSTAGE * AS_STG
    float* Bsm = sm + NSTAGE * AS_STG;     // NSTAGE * BS_STG

    const int tid  = threadIdx.x;
    const int wid  = tid >> 5;
    const int lane = tid & 31;
    const int g    = lane >> 2;
    const int t    = lane & 3;
    const int wm   = wid >> 2;
    const int wn   = wid & 3;

    const float* Ap = A + (size_t)blockIdx.y * 128 * K;
    const float* Bp = Bm + blockIdx.x * 128;

    // loader mapping: 512 16B-chunks for A, 512 for B; 2 each per thread
    const int acid0 = tid * 2;
    const int arow0 = acid0 >> 2,  acc0 = (acid0 & 3) << 2;
    const int arow1 = (acid0 + 1) >> 2, acc1 = ((acid0 + 1) & 3) << 2;
    const int brow0 = acid0 >> 5,  bcc0 = (acid0 & 31) << 2;
    const int brow1 = (acid0 + 1) >> 5, bcc1 = ((acid0 + 1) & 31) << 2;

    float acc[4][4][4];
#pragma unroll
    for (int i = 0; i < 4; ++i)
#pragma unroll
        for (int j = 0; j < 4; ++j)
#pragma unroll
            for (int r = 0; r < 4; ++r) acc[i][j][r] = 0.f;

    // prologue: stages 0..2
#pragma unroll
    for (int ps = 0; ps < NSTAGE - 1; ++ps) {
        const int k0 = ps * 16;
        float* as = Asm + ps * AS_STG;
        float* bs = Bsm + ps * BS_STG;
        CP_ASYNC16((unsigned)__cvta_generic_to_shared(as + arow0 * SA + acc0),
                   Ap + (size_t)arow0 * K + k0 + acc0);
        CP_ASYNC16((unsigned)__cvta_generic_to_shared(as + arow1 * SA + acc1),
                   Ap + (size_t)arow1 * K + k0 + acc1);
        CP_ASYNC16((unsigned)__cvta_generic_to_shared(bs + brow0 * SB + bcc0),
                   Bp + (size_t)(k0 + brow0) * 256 + bcc0);
        CP_ASYNC16((unsigned)__cvta_generic_to_shared(bs + brow1 * SB + bcc1),
                   Bp + (size_t)(k0 + brow1) * 256 + bcc1);
        CP_COMMIT();
    }

    for (int s = 0; s < 16; ++s) {
        CP_WAIT2();
        __syncthreads();

        // prefetch stage s+3 into buffer (s+3)%4 (freed by compute of s-1)
        if (s + NSTAGE - 1 < 16) {
            const int ps = s + NSTAGE - 1;
            const int k0 = ps * 16;
            float* as = Asm + (ps & 3) * AS_STG;
            float* bs = Bsm + (ps & 3) * BS_STG;
            CP_ASYNC16((unsigned)__cvta_generic_to_shared(as + arow0 * SA + acc0),
                       Ap + (size_t)arow0 * K + k0 + acc0);
            CP_ASYNC16((unsigned)__cvta_generic_to_shared(as + arow1 * SA + acc1),
                       Ap + (size_t)arow1 * K + k0 + acc1);
            CP_ASYNC16((unsigned)__cvta_generic_to_shared(bs + brow0 * SB + bcc0),
                       Bp + (size_t)(k0 + brow0) * 256 + bcc0);
            CP_ASYNC16((unsigned)__cvta_generic_to_shared(bs + brow1 * SB + bcc1),
                       Bp + (size_t)(k0 + brow1) * 256 + bcc1);
        }
        CP_COMMIT();   // empty group on tail keeps wait-count uniform

        const float* as = Asm + (s & 3) * AS_STG;
        const float* bs = Bsm + (s & 3) * BS_STG;

#pragma unroll
        for (int ks = 0; ks < 2; ++ks) {
            const int krow = ks * 8 + t;
            unsigned bf0[4], bf1[4];
#pragma unroll
            for (int nt = 0; nt < 4; ++nt) {
                const int col = wn * 32 + nt * 8 + g;
                bf0[nt] = __float_as_uint(bs[krow * SB + col]);        // pre-rounded tf32
                bf1[nt] = __float_as_uint(bs[(krow + 4) * SB + col]);
            }
#pragma unroll
            for (int mt = 0; mt < 4; ++mt) {
                const int row = wm * 64 + mt * 16 + g;
                unsigned a0 = f2tf32(as[row * SA + krow]);
                unsigned a1 = f2tf32(as[(row + 8) * SA + krow]);
                unsigned a2 = f2tf32(as[row * SA + krow + 4]);
                unsigned a3 = f2tf32(as[(row + 8) * SA + krow + 4]);
#pragma unroll
                for (int nt = 0; nt < 4; ++nt)
                    mma_tf32(acc[mt][nt], a0, a1, a2, a3, bf0[nt], bf1[nt]);
            }
        }
    }

    const int rbase = blockIdx.y * 128 + wm * 64;
    const int cbase = blockIdx.x * 128 + wn * 32;
#pragma unroll
    for (int nt = 0; nt < 4; ++nt) {
        const int col = cbase + nt * 8 + 2 * t;
        float b0 = bias ? bias[col] * bscale : 0.f;
        float b1 = bias ? bias[col + 1] * bscale : 0.f;
#pragma unroll
        for (int mt = 0; mt < 4; ++mt) {
            const int row = rbase + mt * 16 + g;
            float2 v0 = make_float2(acc[mt][nt][0] + b0, acc[mt][nt][1] + b1);
            float2 v1 = make_float2(acc[mt][nt][2] + b0, acc[mt][nt][3] + b1);
            *(float2*)(C + (size_t)row * ldc + col)       = v0;
            *(float2*)(C + (size_t)(row + 8) * ldc + col) = v1;
        }
    }
}

// ---------------------------------------------------------------------------
// Gather-reduce + a_feats copy:
//   S[q,:]        = sum_k relu(Q[b,idx_k,:] + P[q,:]) * dw_k
//   out[q, 0:256] = af[q,:]
// ---------------------------------------------------------------------------
__global__ void gather_reduce_copy_kernel(const float* __restrict__ P,
                                          const float* __restrict__ Q,
                                          const int* __restrict__ idx,
                                          const float* __restrict__ dw,
                                          const float* __restrict__ af,
                                          float* __restrict__ out,
                                          float* __restrict__ S) {
    const int tid = threadIdx.x;
    const int q = blockIdx.x * 4 + (tid >> 6);
    const int l = tid & 63;
    const int b = q >> 13;

    ((float4*)out)[(size_t)q * 128 + l] = ((const float4*)af)[(size_t)q * 64 + l];

    const float4* P4 = (const float4*)P;
    const float4* Q4 = (const float4*)Q + (size_t)b * NB_ * 64;

    const float4 p = P4[(size_t)q * 64 + l];
    float4 acc = make_float4(0.f, 0.f, 0.f, 0.f);

#pragma unroll
    for (int k = 0; k < 8; ++k) {
        const int   j = idx[(size_t)q * 8 + k];
        const float w = dw[(size_t)q * 8 + k];
        const float4 v = Q4[(size_t)j * 64 + l];
        acc.x += fmaxf(v.x + p.x, 0.f) * w;
        acc.y += fmaxf(v.y + p.y, 0.f) * w;
        acc.z += fmaxf(v.z + p.z, 0.f) * w;
        acc.w += fmaxf(v.w + p.w, 0.f) * w;
    }
    ((float4*)S)[(size_t)q * 64 + l] = acc;
}

// ---------------------------------------------------------------------------
extern "C" void kernel_launch(void* const* d_in, const int* in_sizes, int n_in,
                              void* d_out, int out_size) {
    const float* af = (const float*)d_in[0];
    const float* bf = (const float*)d_in[1];
    const int*   ca = (const int*)d_in[2];
    const int*   cb = (const int*)d_in[3];
    const float* w1 = (const float*)d_in[4];
    const float* b1 = (const float*)d_in[5];
    const float* w2 = (const float*)d_in[6];
    const float* b2 = (const float*)d_in[7];
    float* out = (float*)d_out;

    float *P, *Q, *S, *WdT, *W1bT, *W2T, *dw;
    int *idx, *ccnt, *cstart, *ccur;
    uint2* pts;
    unsigned* cbp;
    cudaGetSymbolAddress((void**)&P,      g_P);
    cudaGetSymbolAddress((void**)&Q,      g_Q);
    cudaGetSymbolAddress((void**)&S,      g_S);
    cudaGetSymbolAddress((void**)&WdT,    g_WdT);
    cudaGetSymbolAddress((void**)&W1bT,   g_W1bT);
    cudaGetSymbolAddress((void**)&W2T,    g_W2T);
    cudaGetSymbolAddress((void**)&idx,    g_idx);
    cudaGetSymbolAddress((void**)&dw,     g_dw);
    cudaGetSymbolAddress((void**)&ccnt,   g_cellcnt);
    cudaGetSymbolAddress((void**)&cstart, g_cellstart);
    cudaGetSymbolAddress((void**)&ccur,   g_cellcur);
    cudaGetSymbolAddress((void**)&pts,    g_pts);
    cudaGetSymbolAddress((void**)&cbp,    g_cbp);

    cudaFuncSetAttribute(mma_gemm_kernel,
                         cudaFuncAttributeMaxDynamicSharedMemorySize, GEMM_SMEM);

    // 1. spatial grid build
    zero_cnt_kernel<<<B_, NCELL>>>(ccnt);
    hist_kernel<<<(B_ * NB_) / 256, 256>>>(cb, cbp, ccnt);
    scan_kernel<<<B_, NCELL>>>(ccnt, cstart, ccur);
    scatter_kernel<<<(B_ * NB_) / 256, 256>>>(cbp, ccur, pts);

    // 2. exact certified grid kNN
    knn_grid_kernel<<<dim3(NA / 8, B_), 256>>>(ca, cbp, pts, cstart, idx, dw);

    // 3. weight prep (pre-rounded to tf32 grid)
    prep_w_kernel<<<256, 256>>>(w1, w2, WdT, W1bT, W2T);

    // 4. P = af @ W1b^T + b1
    mma_gemm_kernel<<<dim3(2, (B_ * NA) / 128), 256, GEMM_SMEM>>>(af, W1bT, P, 256, b1, 1.f);

    // 5. Q = bf @ (W1a - W1b)^T
    mma_gemm_kernel<<<dim3(2, (B_ * NB_) / 128), 256, GEMM_SMEM>>>(bf, WdT, Q, 256, (const float*)nullptr, 0.f);

    // 6. S = sum_k relu(Q[idx_k] + P) * dw_k ; out[...,0:256] = af
    gather_reduce_copy_kernel<<<(B_ * NA) / 4, 256>>>(P, Q, idx, dw, af, out, S);

    // 7. out[..., 256:512] = S @ W2^T + 8*b2
    mma_gemm_kernel<<<dim3(2, (B_ * NA) / 128), 256, GEMM_SMEM>>>(S, W2T, out + 256, 512, b2, 8.f);
}

// round 11
// speedup vs baseline: 1.1123x; 1.1123x over previous
#include <cuda_runtime.h>
#include <cuda_bf16.h>
#include <math.h>
#include <stdint.h>

// Problem shape (fixed for this problem instance)
#define B_    4
#define NA    8192
#define NB_   8192
#define D_    256
#define TOPK  8
#define NCELL 512      // 8x8x8 grid of cells, cell side 16 (in //16 coords)

// ---------------------------------------------------------------------------
// Scratch (static device globals; no dynamic allocation allowed)
// ---------------------------------------------------------------------------
__device__ float g_P[B_ * NA * D_];        // af @ W1b^T + b1      [32768,256]
__device__ float g_Q[B_ * NB_ * D_];       // bf @ (W1a-W1b)^T     [32768,256]
__device__ float g_S[B_ * NA * D_];        // sum_k relu(Q+P)*dw   [32768,256]
__device__ float g_Wd[D_ * D_];            // [n=d][k=c] = w1[d,c]-w1[d,256+c] (tf32-rounded)
__device__ float g_W1b[D_ * D_];           // [n=d][k=c] = w1[d,256+c]         (tf32-rounded)
__device__ float g_W2r[D_ * D_];           // [n=e][k=d] = w2[e,d]             (tf32-rounded)
__device__ int   g_idx[B_ * NA * TOPK];
__device__ float g_dw[B_ * NA * TOPK];

// spatial grid scratch
__device__ int      g_cellcnt[B_ * NCELL];
__device__ int      g_cellstart[B_ * (NCELL + 1)];
__device__ int      g_cellcur[B_ * NCELL];
__device__ uint2    g_pts[B_ * NB_];       // cell-sorted (packed coord, index)
__device__ unsigned g_cbp[B_ * NB_];       // packed //16 coords, original order

// ---------------------------------------------------------------------------
// tf32 helpers
// ---------------------------------------------------------------------------
__device__ __forceinline__ unsigned f2tf32(float v) {
    unsigned r;
    asm("cvt.rna.tf32.f32 %0, %1;" : "=r"(r) : "f"(v));
    return r;
}

__device__ __forceinline__ void mma_tf32(float* c,
                                         unsigned a0, unsigned a1, unsigned a2, unsigned a3,
                                         unsigned b0, unsigned b1) {
    asm volatile(
        "mma.sync.aligned.m16n8k8.row.col.f32.tf32.tf32.f32 "
        "{%0,%1,%2,%3}, {%4,%5,%6,%7}, {%8,%9}, {%0,%1,%2,%3};"
        : "+f"(c[0]), "+f"(c[1]), "+f"(c[2]), "+f"(c[3])
        : "r"(a0), "r"(a1), "r"(a2), "r"(a3), "r"(b0), "r"(b1));
}

#define CP_ASYNC16(dst_u32, src_ptr) \
    asm volatile("cp.async.cg.shared.global [%0], [%1], 16;" \
                 :: "r"(dst_u32), "l"(src_ptr))
#define CP_COMMIT()  asm volatile("cp.async.commit_group;")
#define CP_WAIT1()   asm volatile("cp.async.wait_group 1;" ::: "memory")
#define CP_WAIT0()   asm volatile("cp.async.wait_group 0;" ::: "memory")

// ---------------------------------------------------------------------------
// Weight preprocessing: B operands ([n][k] row-major), tf32-rounded (rna) so
// the GEMM consumes B fragments without a cvt.
// ---------------------------------------------------------------------------
__global__ void prep_w_kernel(const float* __restrict__ w1,
                              const float* __restrict__ w2,
                              float* __restrict__ Wd,
                              float* __restrict__ W1b,
                              float* __restrict__ W2r) {
    int d = blockIdx.x;
    int c = threadIdx.x;
    float a = w1[d * 512 + c];
    float b = w1[d * 512 + 256 + c];
    Wd[d * 256 + c]  = __uint_as_float(f2tf32(a - b));
    W1b[d * 256 + c] = __uint_as_float(f2tf32(b));
    W2r[d * 256 + c] = __uint_as_float(f2tf32(w2[d * 256 + c]));
}

// ---------------------------------------------------------------------------
// Spatial grid build: zero -> histogram -> scan -> scatter
// ---------------------------------------------------------------------------
__global__ void zero_cnt_kernel(int* __restrict__ cnt) {
    cnt[blockIdx.x * blockDim.x + threadIdx.x] = 0;
}

__global__ void hist_kernel(const int* __restrict__ coords_b,
                            unsigned* __restrict__ cbp,
                            int* __restrict__ cnt) {
    const int i = blockIdx.x * blockDim.x + threadIdx.x;   // 0..B*NB-1
    const int b = i >> 13;
    const int* cb = coords_b + (size_t)i * 3;
    const unsigned x = ((unsigned)cb[0]) >> 4;
    const unsigned y = ((unsigned)cb[1]) >> 4;
    const unsigned z = ((unsigned)cb[2]) >> 4;
    cbp[i] = x | (y << 8) | (z << 16);
    const int cell = (int)(((x >> 4) << 6) | ((y >> 4) << 3) | (z >> 4));
    atomicAdd(&cnt[b * NCELL + cell], 1);
}

__global__ void scan_kernel(const int* __restrict__ cnt,
                            int* __restrict__ cellstart,
                            int* __restrict__ cur) {
    __shared__ int sc[NCELL];
    const int b = blockIdx.x, t = threadIdx.x;
    const int v = cnt[b * NCELL + t];
    sc[t] = v;
    __syncthreads();
    for (int off = 1; off < NCELL; off <<= 1) {
        int x = (t >= off) ? sc[t - off] : 0;
        __syncthreads();
        sc[t] += x;
        __syncthreads();
    }
    cellstart[b * (NCELL + 1) + t + 1] = sc[t];
    if (t == 0) cellstart[b * (NCELL + 1)] = 0;
    cur[b * NCELL + t] = sc[t] - v;   // exclusive
}

__global__ void scatter_kernel(const unsigned* __restrict__ cbp,
                               int* __restrict__ cur,
                               uint2* __restrict__ pts) {
    const int i = blockIdx.x * blockDim.x + threadIdx.x;
    const int b = i >> 13, j = i & 8191;
    const unsigned p = cbp[i];
    const int cell = (int)((((p >> 4) & 7u) << 6) | (((p >> 12) & 7u) << 3) | ((p >> 20) & 7u));
    const int pos = atomicAdd(&cur[b * NCELL + cell], 1);
    pts[(size_t)b * NB_ + pos] = make_uint2(p, (unsigned)j);
}

// ---------------------------------------------------------------------------
// kNN helpers
// ---------------------------------------------------------------------------
__device__ __forceinline__ void insert8(unsigned best[8], unsigned key) {
    if (key < best[7]) {
        best[7] = key;
#pragma unroll
        for (int t = 7; t > 0; --t) {
            unsigned lo = min(best[t - 1], best[t]);
            unsigned hi = max(best[t - 1], best[t]);
            best[t - 1] = lo;
            best[t]     = hi;
        }
    }
}

__device__ __forceinline__ unsigned merge8(unsigned best[8], int lane) {
    unsigned sel = 0;
#pragma unroll
    for (int r = 0; r < 8; ++r) {
        const unsigned v = best[0];
        const unsigned m = __reduce_min_sync(0xFFFFFFFFu, v);
        if (lane == r) sel = m;
        if (v == m) {
#pragma unroll
            for (int t = 0; t < 7; ++t) best[t] = best[t + 1];
            best[7] = 0xFFFFFFFFu;
        }
    }
    return sel;
}

// ---------------------------------------------------------------------------
// Grid kNN: one warp per query; certified exact (brute fallback if the 8th
// neighbor could lie outside the scanned neighborhood).
// ---------------------------------------------------------------------------
__global__ void knn_grid_kernel(const int* __restrict__ coords_a,
                                const unsigned* __restrict__ cbp,
                                const uint2* __restrict__ pts,
                                const int* __restrict__ cellstart,
                                int* __restrict__ idx_out,
                                float* __restrict__ dw_out) {
    const int b = blockIdx.y;
    const int warp = threadIdx.x >> 5;
    const int lane = threadIdx.x & 31;
    const int n = blockIdx.x * 8 + warp;

    const int* ca = coords_a + ((size_t)b * NA + n) * 3;
    const unsigned qx = ((unsigned)ca[0]) >> 4;
    const unsigned qy = ((unsigned)ca[1]) >> 4;
    const unsigned qz = ((unsigned)ca[2]) >> 4;
    const unsigned qp = qx | (qy << 8) | (qz << 16);

    const int cx = (int)(qx >> 4), cy = (int)(qy >> 4), cz = (int)(qz >> 4);
    const int x0 = max(cx - 1, 0), x1 = min(cx + 1, 7);
    const int y0 = max(cy - 1, 0), y1 = min(cy + 1, 7);
    const int z0 = max(cz - 1, 0), z1 = min(cz + 1, 7);

    const int sbase = b * (NCELL + 1);
    const uint2* ptsb = pts + (size_t)b * NB_;

    unsigned best[8];
#pragma unroll
    for (int t = 0; t < 8; ++t) best[t] = 0xFFFFFFFFu;

    for (int x = x0; x <= x1; ++x)
        for (int y = y0; y <= y1; ++y)
            for (int z = z0; z <= z1; ++z) {
                const int c = (x << 6) | (y << 3) | z;
                const int s = __ldg(&cellstart[sbase + c]);
                const int e = __ldg(&cellstart[sbase + c + 1]);
                for (int o = s + lane; o < e; o += 32) {
                    const uint2 pt = ptsb[o];
                    const unsigned ad = __vabsdiffu4(pt.x, qp);
                    const unsigned d2 = (unsigned)__dp4a((int)ad, (int)ad, 0);
                    insert8(best, (d2 << 13) | pt.y);
                }
            }

    unsigned sel = merge8(best, lane);

    const unsigned d2_8 = __shfl_sync(0xFFFFFFFFu, sel, 7) >> 13;
    int mo = 0x7FFFFFFF;
    if (x0 > 0) { int d = (int)qx - (16 * x0 - 1); mo = min(mo, d * d); }
    if (x1 < 7) { int d = 16 * (x1 + 1) - (int)qx; mo = min(mo, d * d); }
    if (y0 > 0) { int d = (int)qy - (16 * y0 - 1); mo = min(mo, d * d); }
    if (y1 < 7) { int d = 16 * (y1 + 1) - (int)qy; mo = min(mo, d * d); }
    if (z0 > 0) { int d = (int)qz - (16 * z0 - 1); mo = min(mo, d * d); }
    if (z1 < 7) { int d = 16 * (z1 + 1) - (int)qz; mo = min(mo, d * d); }

    if (d2_8 >= (unsigned)mo) {   // warp-uniform; vanishingly rare
#pragma unroll
        for (int t = 0; t < 8; ++t) best[t] = 0xFFFFFFFFu;
        const unsigned* cb = cbp + (size_t)b * NB_;
        for (int j = lane; j < NB_; j += 32) {
            const unsigned p = __ldg(&cb[j]);
            const unsigned ad = __vabsdiffu4(p, qp);
            const unsigned d2 = (unsigned)__dp4a((int)ad, (int)ad, 0);
            insert8(best, (d2 << 13) | (unsigned)j);
        }
        sel = merge8(best, lane);
    }

    if (lane < 8) {
        const int j = (int)(sel & 8191u);
        const float dist = sqrtf((float)(sel >> 13)) * (1.0f / 128.0f);
        const float dwv = 0.5f - fminf(dist, 0.5f);
        const size_t o = ((size_t)b * NA + n) * 8 + lane;
        idx_out[o] = j;
        dw_out[o]  = dwv;
    }
}

// ---------------------------------------------------------------------------
// TF32 mma GEMM, occupancy-shaped: C[M,256] = A[M,256] @ Bw^T (+ bscale*bias)
//   Bw: [256][256] row-major [n][k], pre-rounded tf32.
//   Tile 64x128; 256 threads as 2(m) x 4(n) warps; warp tile 32x32; BK=32.
//   2-stage cp.async double buffer; 3 CTAs/SM target (launch_bounds 256,3).
//   PAD=36 words: conflict-free fragment LDS and 16B-aligned cp.async rows.
//   A fragments cvt.rna at consume (af/bf/S raw fp32); accumulation order
//   (k ascending, m16n8k8 chunks) identical to the R6 baseline.
// ---------------------------------------------------------------------------
#define PAD  36
#define ASZ  (64 * PAD)     // 2304 words
#define BSZ  (128 * PAD)    // 4608 words
#define GEMM_SMEM (2 * (ASZ + BSZ) * 4)   // 55,296 bytes

__global__ __launch_bounds__(256, 3)
void mma_gemm_kernel(const float* __restrict__ A, const float* __restrict__ Bw,
                     float* __restrict__ C, int ldc,
                     const float* __restrict__ bias, float bscale) {
    extern __shared__ float sm[];
    float* As0 = sm;             // [2][ASZ]
    float* Bs0 = sm + 2 * ASZ;   // [2][BSZ]

    const int tid  = threadIdx.x;
    const int wid  = tid >> 5;
    const int lane = tid & 31;
    const int g    = lane >> 2;   // groupID 0..7
    const int t    = lane & 3;    // 0..3
    const int wm   = wid >> 2;    // 0..1 (32 rows each)
    const int wn   = wid & 3;     // 0..3 (32 cols each)

    const float* Ap = A  + (size_t)blockIdx.y * 64 * 256;
    const float* Bp = Bw + (size_t)blockIdx.x * 128 * 256;

    // loader: 16B chunks; A tile 64x32 = 512 chunks (2/thread),
    // B tile 128x32 = 1024 chunks (4/thread). (tid+256k)&7 == tid&7.
    const int lrow = tid >> 3;          // 0..31
    const int lcol = (tid & 7) * 4;     // 0,4,...,28
    const uint32_t smA = (uint32_t)__cvta_generic_to_shared(As0);
    const uint32_t smB = (uint32_t)__cvta_generic_to_shared(Bs0);

    float acc[2][4][4];
#pragma unroll
    for (int i = 0; i < 2; ++i)
#pragma unroll
        for (int j = 0; j < 4; ++j)
#pragma unroll
            for (int r = 0; r < 4; ++r) acc[i][j][r] = 0.f;

#define PREFETCH(s) do {                                                        \
    const int k0_ = (s) * 32;                                                   \
    const uint32_t ab_ = smA + (((s) & 1) * ASZ) * 4;                           \
    const uint32_t bb_ = smB + (((s) & 1) * BSZ) * 4;                           \
    CP_ASYNC16(ab_ + (lrow * PAD + lcol) * 4,                                   \
               Ap + (size_t)lrow * 256 + k0_ + lcol);                           \
    CP_ASYNC16(ab_ + ((lrow + 32) * PAD + lcol) * 4,                            \
               Ap + (size_t)(lrow + 32) * 256 + k0_ + lcol);                    \
    _Pragma("unroll")                                                           \
    for (int i_ = 0; i_ < 4; ++i_)                                              \
        CP_ASYNC16(bb_ + ((lrow + 32 * i_) * PAD + lcol) * 4,                   \
                   Bp + (size_t)(lrow + 32 * i_) * 256 + k0_ + lcol);           \
} while (0)

    PREFETCH(0);
    CP_COMMIT();

    for (int s = 0; s < 8; ++s) {
        if (s < 7) {
            PREFETCH(s + 1);    // into buf (s+1)&1, freed by end-of-(s-1) sync
            CP_COMMIT();
            CP_WAIT1();         // stage s group complete; s+1 may be pending
        } else {
            CP_WAIT0();
        }
        __syncthreads();        // cross-thread smem visibility of stage s

        const float* as = As0 + (s & 1) * ASZ;
        const float* bs = Bs0 + (s & 1) * BSZ;

#pragma unroll
        for (int ks = 0; ks < 4; ++ks) {
            const int kt = ks * 8 + t;
            unsigned bf0[4], bf1[4];
#pragma unroll
            for (int nt = 0; nt < 4; ++nt) {
                const int n = wn * 32 + nt * 8 + g;
                bf0[nt] = __float_as_uint(bs[n * PAD + kt]);        // pre-rounded tf32
                bf1[nt] = __float_as_uint(bs[n * PAD + kt + 4]);
            }
#pragma unroll
            for (int mt = 0; mt < 2; ++mt) {
                const int row = wm * 32 + mt * 16 + g;
                unsigned a0 = f2tf32(as[row * PAD + kt]);
                unsigned a1 = f2tf32(as[(row + 8) * PAD + kt]);
                unsigned a2 = f2tf32(as[row * PAD + kt + 4]);
                unsigned a3 = f2tf32(as[(row + 8) * PAD + kt + 4]);
#pragma unroll
                for (int nt = 0; nt < 4; ++nt)
                    mma_tf32(acc[mt][nt], a0, a1, a2, a3, bf0[nt], bf1[nt]);
            }
        }
        __syncthreads();        // stage s fully consumed before its buffer reuse
    }

    // epilogue
    const int rb = blockIdx.y * 64 + wm * 32;
    const int cb = blockIdx.x * 128 + wn * 32;
#pragma unroll
    for (int nt = 0; nt < 4; ++nt) {
        const int col = cb + nt * 8 + 2 * t;
        float b0 = bias ? bias[col] * bscale : 0.f;
        float b1 = bias ? bias[col + 1] * bscale : 0.f;
#pragma unroll
        for (int mt = 0; mt < 2; ++mt) {
            const int row = rb + mt * 16 + g;
            *(float2*)(C + (size_t)row * ldc + col) =
                make_float2(acc[mt][nt][0] + b0, acc[mt][nt][1] + b1);
            *(float2*)(C + (size_t)(row + 8) * ldc + col) =
                make_float2(acc[mt][nt][2] + b0, acc[mt][nt][3] + b1);
        }
    }
#undef PREFETCH
}

// ---------------------------------------------------------------------------
// Gather-reduce + a_feats copy:
//   S[q,:]        = sum_k relu(Q[b,idx_k,:] + P[q,:]) * dw_k
//   out[q, 0:256] = af[q,:]
// ---------------------------------------------------------------------------
__global__ void gather_reduce_copy_kernel(const float* __restrict__ P,
                                          const float* __restrict__ Q,
                                          const int* __restrict__ idx,
                                          const float* __restrict__ dw,
                                          const float* __restrict__ af,
                                          float* __restrict__ out,
                                          float* __restrict__ S) {
    const int tid = threadIdx.x;
    const int q = blockIdx.x * 4 + (tid >> 6);
    const int l = tid & 63;
    const int b = q >> 13;

    ((float4*)out)[(size_t)q * 128 + l] = ((const float4*)af)[(size_t)q * 64 + l];

    const float4* P4 = (const float4*)P;
    const float4* Q4 = (const float4*)Q + (size_t)b * NB_ * 64;

    const float4 p = P4[(size_t)q * 64 + l];
    float4 acc = make_float4(0.f, 0.f, 0.f, 0.f);

#pragma unroll
    for (int k = 0; k < 8; ++k) {
        const int   j = idx[(size_t)q * 8 + k];
        const float w = dw[(size_t)q * 8 + k];
        const float4 v = Q4[(size_t)j * 64 + l];
        acc.x += fmaxf(v.x + p.x, 0.f) * w;
        acc.y += fmaxf(v.y + p.y, 0.f) * w;
        acc.z += fmaxf(v.z + p.z, 0.f) * w;
        acc.w += fmaxf(v.w + p.w, 0.f) * w;
    }
    ((float4*)S)[(size_t)q * 64 + l] = acc;
}

// ---------------------------------------------------------------------------
extern "C" void kernel_launch(void* const* d_in, const int* in_sizes, int n_in,
                              void* d_out, int out_size) {
    const float* af = (const float*)d_in[0];
    const float* bf = (const float*)d_in[1];
    const int*   ca = (const int*)d_in[2];
    const int*   cb = (const int*)d_in[3];
    const float* w1 = (const float*)d_in[4];
    const float* b1 = (const float*)d_in[5];
    const float* w2 = (const float*)d_in[6];
    const float* b2 = (const float*)d_in[7];
    float* out = (float*)d_out;

    float *P, *Q, *S, *Wd, *W1b, *W2r, *dw;
    int *idx, *ccnt, *cstart, *ccur;
    uint2* pts;
    unsigned* cbp;
    cudaGetSymbolAddress((void**)&P,      g_P);
    cudaGetSymbolAddress((void**)&Q,      g_Q);
    cudaGetSymbolAddress((void**)&S,      g_S);
    cudaGetSymbolAddress((void**)&Wd,     g_Wd);
    cudaGetSymbolAddress((void**)&W1b,    g_W1b);
    cudaGetSymbolAddress((void**)&W2r,    g_W2r);
    cudaGetSymbolAddress((void**)&idx,    g_idx);
    cudaGetSymbolAddress((void**)&dw,     g_dw);
    cudaGetSymbolAddress((void**)&ccnt,   g_cellcnt);
    cudaGetSymbolAddress((void**)&cstart, g_cellstart);
    cudaGetSymbolAddress((void**)&ccur,   g_cellcur);
    cudaGetSymbolAddress((void**)&pts,    g_pts);
    cudaGetSymbolAddress((void**)&cbp,    g_cbp);

    cudaFuncSetAttribute(mma_gemm_kernel,
                         cudaFuncAttributeMaxDynamicSharedMemorySize, GEMM_SMEM);

    // 1. spatial grid build
    zero_cnt_kernel<<<B_, NCELL>>>(ccnt);
    hist_kernel<<<(B_ * NB_) / 256, 256>>>(cb, cbp, ccnt);
    scan_kernel<<<B_, NCELL>>>(ccnt, cstart, ccur);
    scatter_kernel<<<(B_ * NB_) / 256, 256>>>(cbp, ccur, pts);

    // 2. exact certified grid kNN
    knn_grid_kernel<<<dim3(NA / 8, B_), 256>>>(ca, cbp, pts, cstart, idx, dw);

    // 3. weight prep ([n][k] B operands, tf32-rounded)
    prep_w_kernel<<<256, 256>>>(w1, w2, Wd, W1b, W2r);

    // 4. P = af @ W1b^T + b1
    mma_gemm_kernel<<<dim3(2, (B_ * NA) / 64), 256, GEMM_SMEM>>>(af, W1b, P, 256, b1, 1.f);

    // 5. Q = bf @ Wd^T
    mma_gemm_kernel<<<dim3(2, (B_ * NB_) / 64), 256, GEMM_SMEM>>>(bf, Wd, Q, 256, (const float*)nullptr, 0.f);

    // 6. S = sum_k relu(Q[idx_k] + P) * dw_k ; out[...,0:256] = af
    gather_reduce_copy_kernel<<<(B_ * NA) / 4, 256>>>(P, Q, idx, dw, af, out, S);

    // 7. out[..., 256:512] = S @ W2r^T + 8*b2
    mma_gemm_kernel<<<dim3(2, (B_ * NA) / 64), 256, GEMM_SMEM>>>(S, W2r, out + 256, 512, b2, 8.f);
}